// round 1
// baseline (speedup 1.0000x reference)
#include <cuda_runtime.h>
#include <math.h>

// Problem constants (fixed by the reference)
#define BB 4
#define LL 2048
#define DD 1024
#define HH 16
#define HD 64

// Scratch (device globals: allocation-free per harness rules)
__device__ float g_qkv[(size_t)BB * LL * 3 * DD];   // [B, L, 3D], q|k|v each head-major
__device__ float g_att[(size_t)BB * LL * DD];       // [B, L, D] attention output

// ---------------------------------------------------------------------------
// SGEMM with bias: C[m][n] = sum_k A[m][k] * W[n][k] + bias[n]
// A: [M,K] row-major, W: [N,K] row-major (torch Linear weight layout)
// Tiles: 128x128x8, 256 threads, 8x8 per-thread micro-tile.
// ---------------------------------------------------------------------------
__global__ __launch_bounds__(256) void sgemm_bias_kernel(
    const float* __restrict__ A, const float* __restrict__ W,
    const float* __restrict__ bias, float* __restrict__ C,
    int M, int N, int K)
{
    __shared__ float As[8][128];
    __shared__ float Ws[8][128];

    const int tid = threadIdx.x;
    const int tx = tid & 15;
    const int ty = tid >> 4;
    const int bm = blockIdx.y * 128;
    const int bn = blockIdx.x * 128;

    const int lr = tid >> 1;          // 0..127
    const int lc = (tid & 1) << 2;    // 0 or 4

    float acc[8][8];
#pragma unroll
    for (int i = 0; i < 8; i++)
#pragma unroll
        for (int j = 0; j < 8; j++) acc[i][j] = 0.0f;

    const float* Ap = A + (size_t)(bm + lr) * K + lc;
    const float* Wp = W + (size_t)(bn + lr) * K + lc;

    for (int k0 = 0; k0 < K; k0 += 8) {
        float4 a4 = *(const float4*)(Ap + k0);
        float4 w4 = *(const float4*)(Wp + k0);
        As[lc + 0][lr] = a4.x; As[lc + 1][lr] = a4.y;
        As[lc + 2][lr] = a4.z; As[lc + 3][lr] = a4.w;
        Ws[lc + 0][lr] = w4.x; Ws[lc + 1][lr] = w4.y;
        Ws[lc + 2][lr] = w4.z; Ws[lc + 3][lr] = w4.w;
        __syncthreads();

#pragma unroll
        for (int kk = 0; kk < 8; kk++) {
            float a[8], w[8];
            *(float4*)&a[0] = *(const float4*)&As[kk][ty << 2];
            *(float4*)&a[4] = *(const float4*)&As[kk][64 + (ty << 2)];
            *(float4*)&w[0] = *(const float4*)&Ws[kk][tx << 2];
            *(float4*)&w[4] = *(const float4*)&Ws[kk][64 + (tx << 2)];
#pragma unroll
            for (int i = 0; i < 8; i++)
#pragma unroll
                for (int j = 0; j < 8; j++)
                    acc[i][j] = fmaf(a[i], w[j], acc[i][j]);
        }
        __syncthreads();
    }

    // Bias (same 8 columns for every row owned by this thread)
    float bv[8];
    const int c0 = bn + (tx << 2);
    const int c1 = bn + 64 + (tx << 2);
#pragma unroll
    for (int j = 0; j < 4; j++) {
        bv[j]     = bias[c0 + j];
        bv[4 + j] = bias[c1 + j];
    }

#pragma unroll
    for (int i = 0; i < 8; i++) {
        const int row = bm + ((i < 4) ? ((ty << 2) + i) : (64 + (ty << 2) + i - 4));
        float* Cr = C + (size_t)row * N;
        float4 o0, o1;
        o0.x = acc[i][0] + bv[0]; o0.y = acc[i][1] + bv[1];
        o0.z = acc[i][2] + bv[2]; o0.w = acc[i][3] + bv[3];
        o1.x = acc[i][4] + bv[4]; o1.y = acc[i][5] + bv[5];
        o1.z = acc[i][6] + bv[6]; o1.w = acc[i][7] + bv[7];
        *(float4*)(Cr + c0) = o0;
        *(float4*)(Cr + c1) = o1;
    }
}

// ---------------------------------------------------------------------------
// Causal flash attention, fp32.
// Grid: (L/64, H, B). Block: 256 threads.
// Each block handles one 64-row q-tile for one (b, h).
// Thread (tx,ty) owns a 4x4 micro-tile: rows ty*4+i, cols tx*4+j.
// Qt, Kt stored [d][row] (transposed) for float4 inner-loop loads.
// P (post-softmax probs) reuses the K smem buffer -> exactly 48KB static smem.
// ---------------------------------------------------------------------------
__global__ __launch_bounds__(256) void attn_kernel(
    const float* __restrict__ qkv, float* __restrict__ out)
{
    __shared__ float Qt[64][64];    // [d][r]
    __shared__ float KtP[64][64];   // [d][c] as K-transposed, then [r][c] as P
    __shared__ float Vs[64][64];    // [c][e]

    const int qt = blockIdx.x;
    const int h  = blockIdx.y;
    const int b  = blockIdx.z;

    const int tid = threadIdx.x;
    const int tx = tid & 15;
    const int ty = tid >> 4;
    const int lr = tid >> 2;            // 0..63 (tile row for loads)
    const int lo = (tid & 3) << 4;      // 0,16,32,48 (dim chunk for loads)

    const size_t rs = 3 * DD;           // qkv row stride in floats
    const float* qbase = qkv + ((size_t)(b * LL) + qt * 64) * rs + h * HD;

    // Load Q tile transposed: Qt[d][r]
#pragma unroll
    for (int i = 0; i < 16; i += 4) {
        float4 v = *(const float4*)(qbase + (size_t)lr * rs + lo + i);
        Qt[lo + i + 0][lr] = v.x;
        Qt[lo + i + 1][lr] = v.y;
        Qt[lo + i + 2][lr] = v.z;
        Qt[lo + i + 3][lr] = v.w;
    }

    float m[4], l[4], o[4][4];
#pragma unroll
    for (int i = 0; i < 4; i++) {
        m[i] = -INFINITY;
        l[i] = 0.0f;
#pragma unroll
        for (int j = 0; j < 4; j++) o[i][j] = 0.0f;
    }

    const float scale = 0.125f;  // 1/sqrt(64)

    for (int jt = 0; jt <= qt; jt++) {
        __syncthreads();  // prev-iter KtP/Vs reads done (and Qt store on iter 0)

        const float* kbase = qkv + ((size_t)(b * LL) + jt * 64) * rs + DD + h * HD;
        const float* vbase = kbase + DD;
#pragma unroll
        for (int i = 0; i < 16; i += 4) {
            float4 kv = *(const float4*)(kbase + (size_t)lr * rs + lo + i);
            KtP[lo + i + 0][lr] = kv.x;
            KtP[lo + i + 1][lr] = kv.y;
            KtP[lo + i + 2][lr] = kv.z;
            KtP[lo + i + 3][lr] = kv.w;
            float4 vv = *(const float4*)(vbase + (size_t)lr * rs + lo + i);
            *(float4*)&Vs[lr][lo + i] = vv;
        }
        __syncthreads();

        // S = Q K^T (4x4 micro-tile per thread)
        float s[4][4];
#pragma unroll
        for (int i = 0; i < 4; i++)
#pragma unroll
            for (int j = 0; j < 4; j++) s[i][j] = 0.0f;

#pragma unroll 8
        for (int d = 0; d < 64; d++) {
            float4 a = *(const float4*)&Qt[d][ty << 2];
            float4 k = *(const float4*)&KtP[d][tx << 2];
            float av[4] = {a.x, a.y, a.z, a.w};
            float kv[4] = {k.x, k.y, k.z, k.w};
#pragma unroll
            for (int i = 0; i < 4; i++)
#pragma unroll
                for (int j = 0; j < 4; j++)
                    s[i][j] = fmaf(av[i], kv[j], s[i][j]);
        }

        // scale + causal mask
        if (jt == qt) {
#pragma unroll
            for (int i = 0; i < 4; i++)
#pragma unroll
                for (int j = 0; j < 4; j++) {
                    if ((tx << 2) + j > (ty << 2) + i) s[i][j] = -INFINITY;
                    else s[i][j] *= scale;
                }
        } else {
#pragma unroll
            for (int i = 0; i < 4; i++)
#pragma unroll
                for (int j = 0; j < 4; j++) s[i][j] *= scale;
        }

        // online softmax per row (row reduction across 16 tx lanes, width 16)
#pragma unroll
        for (int i = 0; i < 4; i++) {
            float mt = fmaxf(fmaxf(s[i][0], s[i][1]), fmaxf(s[i][2], s[i][3]));
#pragma unroll
            for (int off = 8; off >= 1; off >>= 1)
                mt = fmaxf(mt, __shfl_xor_sync(0xffffffffu, mt, off, 16));
            float mn = fmaxf(m[i], mt);
            float alpha = __expf(m[i] - mn);
            m[i] = mn;
            float rsum = 0.0f;
#pragma unroll
            for (int j = 0; j < 4; j++) {
                s[i][j] = __expf(s[i][j] - mn);
                rsum += s[i][j];
            }
#pragma unroll
            for (int off = 8; off >= 1; off >>= 1)
                rsum += __shfl_xor_sync(0xffffffffu, rsum, off, 16);
            l[i] = l[i] * alpha + rsum;
#pragma unroll
            for (int j = 0; j < 4; j++) o[i][j] *= alpha;
        }

        __syncthreads();  // everyone done reading KtP as K

        // store P into KtP as [r][c]
#pragma unroll
        for (int i = 0; i < 4; i++) {
            float4 p4 = make_float4(s[i][0], s[i][1], s[i][2], s[i][3]);
            *(float4*)&KtP[(ty << 2) + i][tx << 2] = p4;
        }
        __syncthreads();

        // O += P V  (thread owns rows ty*4+i, output dims tx*4+j)
#pragma unroll 8
        for (int c = 0; c < 64; c++) {
            float4 v = *(const float4*)&Vs[c][tx << 2];
#pragma unroll
            for (int i = 0; i < 4; i++) {
                float p = KtP[(ty << 2) + i][c];
                o[i][0] = fmaf(p, v.x, o[i][0]);
                o[i][1] = fmaf(p, v.y, o[i][1]);
                o[i][2] = fmaf(p, v.z, o[i][2]);
                o[i][3] = fmaf(p, v.w, o[i][3]);
            }
        }
    }

    // epilogue: normalize and write [B, L, D] with d = h*64 + e
    float* obase = out + ((size_t)(b * LL) + qt * 64) * DD + h * HD;
#pragma unroll
    for (int i = 0; i < 4; i++) {
        const int row = (ty << 2) + i;
        const float inv = 1.0f / l[i];
        float4 r;
        r.x = o[i][0] * inv; r.y = o[i][1] * inv;
        r.z = o[i][2] * inv; r.w = o[i][3] * inv;
        *(float4*)(obase + (size_t)row * DD + (tx << 2)) = r;
    }
}

// ---------------------------------------------------------------------------
extern "C" void kernel_launch(void* const* d_in, const int* in_sizes, int n_in,
                              void* d_out, int out_size)
{
    const float* x     = (const float*)d_in[0];   // [B, L, D]
    const float* Wqkv  = (const float*)d_in[1];   // [3D, D]
    const float* bqkv  = (const float*)d_in[2];   // [3D]
    const float* Wout  = (const float*)d_in[3];   // [D, D]
    const float* bout  = (const float*)d_in[4];   // [D]
    float* outp = (float*)d_out;                  // [B, L, D]

    float* qkv = nullptr;
    float* att = nullptr;
    cudaGetSymbolAddress((void**)&qkv, g_qkv);
    cudaGetSymbolAddress((void**)&att, g_att);

    const int M = BB * LL;       // 8192

    // 1) QKV projection: [M, 3D] = x[M, D] * Wqkv^T + bqkv
    {
        dim3 grid((3 * DD) / 128, M / 128);
        sgemm_bias_kernel<<<grid, 256>>>(x, Wqkv, bqkv, qkv, M, 3 * DD, DD);
    }

    // 2) causal attention per (b, h, q-tile)
    {
        dim3 grid(LL / 64, HH, BB);
        attn_kernel<<<grid, 256>>>(qkv, att);
    }

    // 3) output projection: [M, D] = att[M, D] * Wout^T + bout
    {
        dim3 grid(DD / 128, M / 128);
        sgemm_bias_kernel<<<grid, 256>>>(att, Wout, bout, outp, M, DD, DD);
    }
}

// round 2
// speedup vs baseline: 2.2243x; 2.2243x over previous
#include <cuda_runtime.h>
#include <math.h>
#include <stdint.h>

#define BB 4
#define LL 2048
#define DD 1024
#define HH 16
#define HD 64

__device__ float g_qkv[(size_t)BB * LL * 3 * DD];   // [B, L, 3D]
__device__ float g_att[(size_t)BB * LL * DD];       // [B, L, D]

__device__ __forceinline__ uint32_t f2tf32(float x) {
    uint32_t r;
    asm("cvt.rna.tf32.f32 %0, %1;" : "=r"(r) : "f"(x));
    return r;
}

// D += A @ B, m16n8k8 tf32. A frag: a0=(r,c) a1=(r+8,c) a2=(r,c+4) a3=(r+8,c+4)
// B frag: b0=(k=lane%4, n=lane/4), b1=(k+4, n). C: c0=(r,2c) c1=(r,2c+1) c2,c3=+8row.
__device__ __forceinline__ void mma_tf32(float* d, const uint32_t* a,
                                         uint32_t b0, uint32_t b1) {
    asm volatile(
        "mma.sync.aligned.m16n8k8.row.col.f32.tf32.tf32.f32 "
        "{%0,%1,%2,%3}, {%4,%5,%6,%7}, {%8,%9}, {%0,%1,%2,%3};\n"
        : "+f"(d[0]), "+f"(d[1]), "+f"(d[2]), "+f"(d[3])
        : "r"(a[0]), "r"(a[1]), "r"(a[2]), "r"(a[3]), "r"(b0), "r"(b1));
}

// ---------------------------------------------------------------------------
// tf32 GEMM with bias: C[m][n] = sum_k A[m][k]*W[n][k] + bias[n]
// A:[M,K] rm, W:[N,K] rm. Block 128x128, kTile 16, 8 warps (2x4), warp 64x32.
// Smem [128][20] stride-20: fragment LDS conflict-free.
// ---------------------------------------------------------------------------
__global__ __launch_bounds__(256, 2) void sgemm_tf32_bias(
    const float* __restrict__ A, const float* __restrict__ W,
    const float* __restrict__ bias, float* __restrict__ C,
    int M, int N, int K)
{
    __shared__ uint32_t As[128 * 20];
    __shared__ uint32_t Ws[128 * 20];

    const int tid = threadIdx.x;
    const int lane = tid & 31;
    const int ww = tid >> 5;
    const int wr = ww >> 2;          // 0..1
    const int wc = ww & 3;           // 0..3
    const int qr = lane >> 2;        // 0..7
    const int qc = lane & 3;         // 0..3
    const int bm = blockIdx.y * 128;
    const int bn = blockIdx.x * 128;

    float acc[16][4];
#pragma unroll
    for (int i = 0; i < 16; i++)
#pragma unroll
        for (int j = 0; j < 4; j++) acc[i][j] = 0.0f;

    const int lrow = tid >> 1;           // 0..127
    const int lk = (tid & 1) * 8;        // 0 or 8
    const float* Ap = A + (size_t)(bm + lrow) * K + lk;
    const float* Wp = W + (size_t)(bn + lrow) * K + lk;

    for (int kt = 0; kt < K; kt += 16) {
        float4 a0 = *(const float4*)(Ap + kt);
        float4 a1 = *(const float4*)(Ap + kt + 4);
        float4 w0 = *(const float4*)(Wp + kt);
        float4 w1 = *(const float4*)(Wp + kt + 4);

        __syncthreads();
        uint32_t* ad = &As[lrow * 20 + lk];
        ad[0] = f2tf32(a0.x); ad[1] = f2tf32(a0.y);
        ad[2] = f2tf32(a0.z); ad[3] = f2tf32(a0.w);
        ad[4] = f2tf32(a1.x); ad[5] = f2tf32(a1.y);
        ad[6] = f2tf32(a1.z); ad[7] = f2tf32(a1.w);
        uint32_t* wd = &Ws[lrow * 20 + lk];
        wd[0] = f2tf32(w0.x); wd[1] = f2tf32(w0.y);
        wd[2] = f2tf32(w0.z); wd[3] = f2tf32(w0.w);
        wd[4] = f2tf32(w1.x); wd[5] = f2tf32(w1.y);
        wd[6] = f2tf32(w1.z); wd[7] = f2tf32(w1.w);
        __syncthreads();

#pragma unroll
        for (int ks = 0; ks < 16; ks += 8) {
            uint32_t aa[4][4], bb[4][2];
#pragma unroll
            for (int mi = 0; mi < 4; mi++) {
                const int m = wr * 64 + mi * 16 + qr;
                aa[mi][0] = As[m * 20 + ks + qc];
                aa[mi][1] = As[(m + 8) * 20 + ks + qc];
                aa[mi][2] = As[m * 20 + ks + 4 + qc];
                aa[mi][3] = As[(m + 8) * 20 + ks + 4 + qc];
            }
#pragma unroll
            for (int ni = 0; ni < 4; ni++) {
                const int n = wc * 32 + ni * 8 + qr;
                bb[ni][0] = Ws[n * 20 + ks + qc];
                bb[ni][1] = Ws[n * 20 + ks + 4 + qc];
            }
#pragma unroll
            for (int mi = 0; mi < 4; mi++)
#pragma unroll
                for (int ni = 0; ni < 4; ni++)
                    mma_tf32(acc[mi * 4 + ni], aa[mi], bb[ni][0], bb[ni][1]);
        }
    }

#pragma unroll
    for (int mi = 0; mi < 4; mi++) {
        const int row = bm + wr * 64 + mi * 16 + qr;
#pragma unroll
        for (int ni = 0; ni < 4; ni++) {
            const int col = bn + wc * 32 + ni * 8 + qc * 2;
            const float b0 = bias[col], b1 = bias[col + 1];
            float* d = acc[mi * 4 + ni];
            float2 r0 = make_float2(d[0] + b0, d[1] + b1);
            float2 r1 = make_float2(d[2] + b0, d[3] + b1);
            *(float2*)(C + (size_t)row * N + col) = r0;
            *(float2*)(C + (size_t)(row + 8) * N + col) = r1;
        }
    }
}

// ---------------------------------------------------------------------------
// Causal flash attention, tf32 mma. Grid (L/64, H, B), block 128 (4 warps).
// Warp w owns q rows [w*16, w*16+16). Q fragments register-resident.
// Kt stored [d][seq] stride 72; P overlays Kt buffer at stride 68;
// V stored [seq][hd] stride 72. All fragment LDS bank-conflict-free.
// ---------------------------------------------------------------------------
__global__ __launch_bounds__(128) void attn_tf32_kernel(
    const float* __restrict__ qkv, float* __restrict__ out)
{
    __shared__ uint32_t KtPs[64 * 72];
    __shared__ uint32_t Vsm[64 * 72];

    const int qt = blockIdx.x;
    const int h  = blockIdx.y;
    const int b  = blockIdx.z;

    const int tid = threadIdx.x;
    const int lane = tid & 31;
    const int w = tid >> 5;
    const int qr = lane >> 2;     // 0..7
    const int qc = lane & 3;      // 0..3

    const size_t rs = 3 * DD;

    // Register-resident Q fragments (tf32)
    uint32_t qa[8][4];
    const float* qb = qkv + ((size_t)(b * LL + qt * 64 + w * 16)) * rs + h * HD;
#pragma unroll
    for (int ks = 0; ks < 8; ks++) {
        const int d = ks * 8 + qc;
        qa[ks][0] = f2tf32(qb[(size_t)qr * rs + d]);
        qa[ks][1] = f2tf32(qb[(size_t)(qr + 8) * rs + d]);
        qa[ks][2] = f2tf32(qb[(size_t)qr * rs + d + 4]);
        qa[ks][3] = f2tf32(qb[(size_t)(qr + 8) * rs + d + 4]);
    }

    float o[8][4];
#pragma unroll
    for (int j = 0; j < 8; j++)
#pragma unroll
        for (int c = 0; c < 4; c++) o[j][c] = 0.0f;
    float m0 = -INFINITY, m1 = -INFINITY, l0 = 0.0f, l1 = 0.0f;

    const int lr = tid & 63;      // KV load row
    const int lh = tid >> 6;      // 0/1 column half
    const float scale = 0.125f;   // 1/sqrt(64)
    const int qrow0 = qt * 64 + w * 16 + qr;
    const int qrow1 = qrow0 + 8;

    for (int jt = 0; jt <= qt; jt++) {
        __syncthreads();
        const float* kb = qkv + ((size_t)(b * LL + jt * 64)) * rs + DD + h * HD;
        const float* vb = kb + DD;
#pragma unroll
        for (int i = 0; i < 8; i++) {
            const int c = lh * 32 + i * 4;
            float4 kv = *(const float4*)(kb + (size_t)lr * rs + c);
            KtPs[(c + 0) * 72 + lr] = f2tf32(kv.x);
            KtPs[(c + 1) * 72 + lr] = f2tf32(kv.y);
            KtPs[(c + 2) * 72 + lr] = f2tf32(kv.z);
            KtPs[(c + 3) * 72 + lr] = f2tf32(kv.w);
            float4 vv = *(const float4*)(vb + (size_t)lr * rs + c);
            uint32_t* vd = &Vsm[lr * 72 + c];
            vd[0] = f2tf32(vv.x); vd[1] = f2tf32(vv.y);
            vd[2] = f2tf32(vv.z); vd[3] = f2tf32(vv.w);
        }
        __syncthreads();

        // S = Q @ K^T
        float s[8][4];
#pragma unroll
        for (int j = 0; j < 8; j++)
#pragma unroll
            for (int c = 0; c < 4; c++) s[j][c] = 0.0f;
#pragma unroll
        for (int ks = 0; ks < 8; ks++) {
#pragma unroll
            for (int j = 0; j < 8; j++) {
                uint32_t b0 = KtPs[(ks * 8 + qc) * 72 + j * 8 + qr];
                uint32_t b1 = KtPs[(ks * 8 + 4 + qc) * 72 + j * 8 + qr];
                mma_tf32(s[j], qa[ks], b0, b1);
            }
        }

        // scale + causal mask (cols > row masked); always-safe comparison
#pragma unroll
        for (int j = 0; j < 8; j++) {
            const int c0 = jt * 64 + j * 8 + qc * 2;
            s[j][0] = (c0     <= qrow0) ? s[j][0] * scale : -INFINITY;
            s[j][1] = (c0 + 1 <= qrow0) ? s[j][1] * scale : -INFINITY;
            s[j][2] = (c0     <= qrow1) ? s[j][2] * scale : -INFINITY;
            s[j][3] = (c0 + 1 <= qrow1) ? s[j][3] * scale : -INFINITY;
        }

        // online softmax: rows qrow0 (c0,c1), qrow1 (c2,c3); reduce over quad
        float mt0 = -INFINITY, mt1 = -INFINITY;
#pragma unroll
        for (int j = 0; j < 8; j++) {
            mt0 = fmaxf(mt0, fmaxf(s[j][0], s[j][1]));
            mt1 = fmaxf(mt1, fmaxf(s[j][2], s[j][3]));
        }
#pragma unroll
        for (int off = 1; off <= 2; off <<= 1) {
            mt0 = fmaxf(mt0, __shfl_xor_sync(0xffffffffu, mt0, off));
            mt1 = fmaxf(mt1, __shfl_xor_sync(0xffffffffu, mt1, off));
        }
        const float mn0 = fmaxf(m0, mt0);
        const float mn1 = fmaxf(m1, mt1);
        const float al0 = __expf(m0 - mn0);
        const float al1 = __expf(m1 - mn1);
        m0 = mn0; m1 = mn1;

        float rs0 = 0.0f, rs1 = 0.0f;
#pragma unroll
        for (int j = 0; j < 8; j++) {
            s[j][0] = __expf(s[j][0] - mn0);
            s[j][1] = __expf(s[j][1] - mn0);
            s[j][2] = __expf(s[j][2] - mn1);
            s[j][3] = __expf(s[j][3] - mn1);
            rs0 += s[j][0] + s[j][1];
            rs1 += s[j][2] + s[j][3];
        }
#pragma unroll
        for (int off = 1; off <= 2; off <<= 1) {
            rs0 += __shfl_xor_sync(0xffffffffu, rs0, off);
            rs1 += __shfl_xor_sync(0xffffffffu, rs1, off);
        }
        l0 = l0 * al0 + rs0;
        l1 = l1 * al1 + rs1;
#pragma unroll
        for (int j = 0; j < 8; j++) {
            o[j][0] *= al0; o[j][1] *= al0;
            o[j][2] *= al1; o[j][3] *= al1;
        }

        __syncthreads();  // all warps done reading Kt

        // store P (tf32) into Kt buffer at stride 68
        const int prow = w * 16 + qr;
#pragma unroll
        for (int j = 0; j < 8; j++) {
            const int col = j * 8 + qc * 2;
            uint32_t* p0 = &KtPs[prow * 68 + col];
            p0[0] = f2tf32(s[j][0]); p0[1] = f2tf32(s[j][1]);
            uint32_t* p1 = &KtPs[(prow + 8) * 68 + col];
            p1[0] = f2tf32(s[j][2]); p1[1] = f2tf32(s[j][3]);
        }
        __syncthreads();

        // O += P @ V
#pragma unroll
        for (int ks = 0; ks < 8; ks++) {
            uint32_t pa[4];
            pa[0] = KtPs[prow * 68 + ks * 8 + qc];
            pa[1] = KtPs[(prow + 8) * 68 + ks * 8 + qc];
            pa[2] = KtPs[prow * 68 + ks * 8 + 4 + qc];
            pa[3] = KtPs[(prow + 8) * 68 + ks * 8 + 4 + qc];
#pragma unroll
            for (int j = 0; j < 8; j++) {
                uint32_t vb0 = Vsm[(ks * 8 + qc) * 72 + j * 8 + qr];
                uint32_t vb1 = Vsm[(ks * 8 + 4 + qc) * 72 + j * 8 + qr];
                mma_tf32(o[j], pa, vb0, vb1);
            }
        }
    }

    // epilogue
    const float inv0 = 1.0f / l0;
    const float inv1 = 1.0f / l1;
    float* ob = out + ((size_t)(b * LL + qt * 64 + w * 16)) * DD + h * HD;
#pragma unroll
    for (int j = 0; j < 8; j++) {
        const int col = j * 8 + qc * 2;
        float2 r0 = make_float2(o[j][0] * inv0, o[j][1] * inv0);
        float2 r1 = make_float2(o[j][2] * inv1, o[j][3] * inv1);
        *(float2*)(ob + (size_t)qr * DD + col) = r0;
        *(float2*)(ob + (size_t)(qr + 8) * DD + col) = r1;
    }
}

// ---------------------------------------------------------------------------
extern "C" void kernel_launch(void* const* d_in, const int* in_sizes, int n_in,
                              void* d_out, int out_size)
{
    const float* x    = (const float*)d_in[0];
    const float* Wqkv = (const float*)d_in[1];
    const float* bqkv = (const float*)d_in[2];
    const float* Wout = (const float*)d_in[3];
    const float* bout = (const float*)d_in[4];
    float* outp = (float*)d_out;

    float* qkv = nullptr;
    float* att = nullptr;
    cudaGetSymbolAddress((void**)&qkv, g_qkv);
    cudaGetSymbolAddress((void**)&att, g_att);

    const int M = BB * LL;  // 8192

    {
        dim3 grid((3 * DD) / 128, M / 128);
        sgemm_tf32_bias<<<grid, 256>>>(x, Wqkv, bqkv, qkv, M, 3 * DD, DD);
    }
    {
        dim3 grid(LL / 64, HH, BB);
        attn_tf32_kernel<<<grid, 128>>>(qkv, att);
    }
    {
        dim3 grid(DD / 128, M / 128);
        sgemm_tf32_bias<<<grid, 256>>>(att, Wout, bout, outp, M, DD, DD);
    }
}

// round 3
// speedup vs baseline: 3.6630x; 1.6468x over previous
#include <cuda_runtime.h>
#include <math.h>
#include <stdint.h>

#define BB 4
#define LL 2048
#define DD 1024
#define HH 16
#define HD 64

// Scratch (device globals)
__device__ float    g_qkv[(size_t)BB * LL * 3 * DD];   // tf32 bits (Q pre-scaled)
__device__ float    g_att[(size_t)BB * LL * DD];       // tf32 bits
__device__ uint32_t g_xt  [(size_t)BB * LL * DD];      // x as tf32
__device__ uint32_t g_wq  [(size_t)3 * DD * DD];       // Wqkv as tf32
__device__ uint32_t g_wo  [(size_t)DD * DD];           // Wout as tf32

__device__ __forceinline__ uint32_t f2tf32(float x) {
    uint32_t r;
    asm("cvt.rna.tf32.f32 %0, %1;" : "=r"(r) : "f"(x));
    return r;
}

__device__ __forceinline__ void cp_async16(uint32_t smem_addr, const void* gptr) {
    asm volatile("cp.async.cg.shared.global [%0], [%1], 16;\n"
                 :: "r"(smem_addr), "l"(gptr));
}
__device__ __forceinline__ void cp_commit() {
    asm volatile("cp.async.commit_group;\n" ::: "memory");
}
template <int N>
__device__ __forceinline__ void cp_wait() {
    asm volatile("cp.async.wait_group %0;\n" :: "n"(N) : "memory");
}

// m16n8k8 tf32 mma. A frag: a0=(r,qc) a1=(r+8,qc) a2=(r,qc+4) a3=(r+8,qc+4)
// B frag: b0=(k=qc,n=qr) b1=(k=qc+4,n=qr). C: c0=(r,2qc) c1=(r,2qc+1) c2/c3 = +8 rows.
__device__ __forceinline__ void mma_tf32(float* d, const uint32_t* a,
                                         uint32_t b0, uint32_t b1) {
    asm volatile(
        "mma.sync.aligned.m16n8k8.row.col.f32.tf32.tf32.f32 "
        "{%0,%1,%2,%3}, {%4,%5,%6,%7}, {%8,%9}, {%0,%1,%2,%3};\n"
        : "+f"(d[0]), "+f"(d[1]), "+f"(d[2]), "+f"(d[3])
        : "r"(a[0]), "r"(a[1]), "r"(a[2]), "r"(a[3]), "r"(b0), "r"(b1));
}

// ---------------------------------------------------------------------------
// tf32 prepass
// ---------------------------------------------------------------------------
__global__ void to_tf32_kernel(const float4* __restrict__ in,
                               uint4* __restrict__ out, int n4) {
    int i = blockIdx.x * blockDim.x + threadIdx.x;
    if (i < n4) {
        float4 v = in[i];
        uint4 r;
        r.x = f2tf32(v.x); r.y = f2tf32(v.y);
        r.z = f2tf32(v.z); r.w = f2tf32(v.w);
        out[i] = r;
    }
}

// ---------------------------------------------------------------------------
// tf32 GEMM, C = A @ W^T + bias. A:[M,K] tf32 bits, W:[N,K] tf32 bits.
// Block 128x128, kTile 16, 4 warps (2x2), warp 64x64 (mi=4, ni=8).
// Double-buffered cp.async. Smem stride 20 words: fragment LDS conflict-free.
// MODE 0: fp32 out. MODE 1: tf32-bits out, Q columns (<DD) scaled by 0.125.
// ---------------------------------------------------------------------------
template <int MODE>
__global__ __launch_bounds__(128) void gemm_tf32(
    const uint32_t* __restrict__ A, const uint32_t* __restrict__ W,
    const float* __restrict__ bias, float* __restrict__ C,
    int M, int N, int K)
{
    __shared__ uint32_t As[2][128 * 20];
    __shared__ uint32_t Ws[2][128 * 20];

    const int tid = threadIdx.x;
    const int lane = tid & 31;
    const int ww = tid >> 5;
    const int wr = ww >> 1;          // 0..1
    const int wc = ww & 1;           // 0..1
    const int qr = lane >> 2;        // 0..7
    const int qc = lane & 3;         // 0..3
    const int bm = blockIdx.y * 128;
    const int bn = blockIdx.x * 128;

    float acc[4][8][4];
#pragma unroll
    for (int i = 0; i < 4; i++)
#pragma unroll
        for (int j = 0; j < 8; j++)
#pragma unroll
            for (int c = 0; c < 4; c++) acc[i][j][c] = 0.0f;

    // cp.async staging map: 1024 chunks of 16B (512 A + 512 W), 8 per thread.
    // chunk q: r = (q&511)>>2, c = q&3. smem word = r*20 + c*4.
    uint32_t as_base[2], ws_base[2];
    as_base[0] = (uint32_t)__cvta_generic_to_shared(&As[0][0]);
    as_base[1] = (uint32_t)__cvta_generic_to_shared(&As[1][0]);
    ws_base[0] = (uint32_t)__cvta_generic_to_shared(&Ws[0][0]);
    ws_base[1] = (uint32_t)__cvta_generic_to_shared(&Ws[1][0]);

    const int nkt = K / 16;

    auto stage = [&](int kt_idx, int s) {
#pragma unroll
        for (int i = 0; i < 8; i++) {
            const int q = i * 128 + tid;
            const int r = (q & 511) >> 2;
            const int c = q & 3;
            const uint32_t soff = (uint32_t)(r * 20 + c * 4) * 4u;
            if (q < 512) {
                const uint32_t* g = A + (size_t)(bm + r) * K + kt_idx * 16 + c * 4;
                cp_async16(as_base[s] + soff, g);
            } else {
                const uint32_t* g = W + (size_t)(bn + r) * K + kt_idx * 16 + c * 4;
                cp_async16(ws_base[s] + soff, g);
            }
        }
        cp_commit();
    };

    stage(0, 0);

    for (int kt = 0; kt < nkt; kt++) {
        const int s = kt & 1;
        if (kt + 1 < nkt) { stage(kt + 1, s ^ 1); cp_wait<1>(); }
        else             { cp_wait<0>(); }
        __syncthreads();

#pragma unroll
        for (int ks = 0; ks < 16; ks += 8) {
            uint32_t aa[4][4], bb[8][2];
#pragma unroll
            for (int mi = 0; mi < 4; mi++) {
                const int m = wr * 64 + mi * 16 + qr;
                aa[mi][0] = As[s][m * 20 + ks + qc];
                aa[mi][1] = As[s][(m + 8) * 20 + ks + qc];
                aa[mi][2] = As[s][m * 20 + ks + 4 + qc];
                aa[mi][3] = As[s][(m + 8) * 20 + ks + 4 + qc];
            }
#pragma unroll
            for (int ni = 0; ni < 8; ni++) {
                const int n = wc * 64 + ni * 8 + qr;
                bb[ni][0] = Ws[s][n * 20 + ks + qc];
                bb[ni][1] = Ws[s][n * 20 + ks + 4 + qc];
            }
#pragma unroll
            for (int mi = 0; mi < 4; mi++)
#pragma unroll
                for (int ni = 0; ni < 8; ni++)
                    mma_tf32(acc[mi][ni], aa[mi], bb[ni][0], bb[ni][1]);
        }
        __syncthreads();
    }

#pragma unroll
    for (int mi = 0; mi < 4; mi++) {
        const int row = bm + wr * 64 + mi * 16 + qr;
#pragma unroll
        for (int ni = 0; ni < 8; ni++) {
            const int col = bn + wc * 64 + ni * 8 + qc * 2;
            const float b0 = bias[col], b1 = bias[col + 1];
            float* d = acc[mi][ni];
            float v00 = d[0] + b0, v01 = d[1] + b1;
            float v10 = d[2] + b0, v11 = d[3] + b1;
            if (MODE == 1) {
                const float sc = (col < DD) ? 0.125f : 1.0f;
                v00 = __uint_as_float(f2tf32(v00 * sc));
                v01 = __uint_as_float(f2tf32(v01 * sc));
                v10 = __uint_as_float(f2tf32(v10 * sc));
                v11 = __uint_as_float(f2tf32(v11 * sc));
            }
            *(float2*)(C + (size_t)row * N + col)       = make_float2(v00, v01);
            *(float2*)(C + (size_t)(row + 8) * N + col) = make_float2(v10, v11);
        }
    }
}

// ---------------------------------------------------------------------------
// Causal flash attention, tf32 mma. Grid (L/128, H, B) with qt reversed,
// block 128 (4 warps). Warp w owns q rows [w*32, w*32+32) (mi=2).
// Dynamic smem: K 2x[64][68], V 2x[64][72], P [128][68] (words).
// All fragment LDS conflict-free by stride choice (68 = 4 mod 32, 72 = 8 mod 32).
// qkv holds tf32 bits with Q pre-scaled by 0.125.
// ---------------------------------------------------------------------------
#define KST 68
#define VST 72
#define K_WORDS (64 * KST)
#define V_WORDS (64 * VST)
#define OFF_K0 0
#define OFF_V0 (2 * K_WORDS)
#define OFF_P  (2 * K_WORDS + 2 * V_WORDS)
#define SMEM_ATTN ((2 * K_WORDS + 2 * V_WORDS + 128 * KST) * 4)

__global__ __launch_bounds__(128) void attn_tf32_kernel(
    const float* __restrict__ qkvf, float* __restrict__ out)
{
    extern __shared__ uint32_t sm[];
    const uint32_t* qkv = (const uint32_t*)qkvf;

    const int qt = gridDim.x - 1 - blockIdx.x;   // big tiles first
    const int h  = blockIdx.y;
    const int b  = blockIdx.z;

    const int tid = threadIdx.x;
    const int lane = tid & 31;
    const int w = tid >> 5;
    const int qr = lane >> 2;
    const int qc = lane & 3;

    const size_t rs = 3 * DD;
    const uint32_t sm_base = (uint32_t)__cvta_generic_to_shared(sm);

    // Q fragments, register resident (already tf32 + scaled)
    uint32_t qa[2][8][4];
    const uint32_t* qb = qkv + ((size_t)(b * LL + qt * 128 + w * 32)) * rs + h * HD;
#pragma unroll
    for (int mi = 0; mi < 2; mi++)
#pragma unroll
        for (int ks = 0; ks < 8; ks++) {
            const int d = ks * 8 + qc;
            const size_t r0 = (size_t)(mi * 16 + qr) * rs;
            qa[mi][ks][0] = qb[r0 + d];
            qa[mi][ks][1] = qb[r0 + 8 * rs + d];
            qa[mi][ks][2] = qb[r0 + d + 4];
            qa[mi][ks][3] = qb[r0 + 8 * rs + d + 4];
        }

    float o[2][8][4];
    float m[2][2], l[2][2];
#pragma unroll
    for (int mi = 0; mi < 2; mi++) {
        m[mi][0] = m[mi][1] = -INFINITY;
        l[mi][0] = l[mi][1] = 0.0f;
#pragma unroll
        for (int j = 0; j < 8; j++)
#pragma unroll
            for (int c = 0; c < 4; c++) o[mi][j][c] = 0.0f;
    }

    const int jmax = 2 * qt + 1;

    auto stage = [&](int jt, int s) {
        const uint32_t* kg = qkv + ((size_t)(b * LL + jt * 64)) * rs + DD + h * HD;
        const uint32_t* vg = kg + DD;
        // 2048 chunks of 16B (1024 K + 1024 V), 16 per thread
#pragma unroll
        for (int i = 0; i < 8; i++) {
            const int q = i * 128 + tid;        // K chunk
            const int r = q >> 4, c = q & 15;
            cp_async16(sm_base + (uint32_t)((OFF_K0 + s * K_WORDS + r * KST + c * 4) * 4),
                       kg + (size_t)r * rs + c * 4);
        }
#pragma unroll
        for (int i = 0; i < 8; i++) {
            const int q = i * 128 + tid;        // V chunk
            const int r = q >> 4, c = q & 15;
            cp_async16(sm_base + (uint32_t)((OFF_V0 + s * V_WORDS + r * VST + c * 4) * 4),
                       vg + (size_t)r * rs + c * 4);
        }
        cp_commit();
    };

    stage(0, 0);

    for (int jt = 0; jt <= jmax; jt++) {
        const int s = jt & 1;
        __syncthreads();   // protect stage s^1 (read 2 iters ago) before rewrite
        if (jt + 1 <= jmax) { stage(jt + 1, s ^ 1); cp_wait<1>(); }
        else                { cp_wait<0>(); }
        __syncthreads();

        const uint32_t* Ks = sm + OFF_K0 + s * K_WORDS;
        const uint32_t* Vs = sm + OFF_V0 + s * V_WORDS;
        uint32_t* Ps = sm + OFF_P;

        const int wrow_min = qt * 128 + w * 32;
        const bool tile_dead = (jt * 64) > (wrow_min + 31);

        if (!tile_dead) {
            // S = Q K^T
            float sreg[2][8][4];
#pragma unroll
            for (int mi = 0; mi < 2; mi++)
#pragma unroll
                for (int j = 0; j < 8; j++)
#pragma unroll
                    for (int c = 0; c < 4; c++) sreg[mi][j][c] = 0.0f;

#pragma unroll
            for (int ks = 0; ks < 8; ks++) {
#pragma unroll
                for (int j = 0; j < 8; j++) {
                    const uint32_t b0 = Ks[(j * 8 + qr) * KST + ks * 8 + qc];
                    const uint32_t b1 = Ks[(j * 8 + qr) * KST + ks * 8 + 4 + qc];
                    mma_tf32(sreg[0][j], qa[0][ks], b0, b1);
                    mma_tf32(sreg[1][j], qa[1][ks], b0, b1);
                }
            }

            // causal mask (only needed near the diagonal); warp-uniform check
            if ((jt + 1) * 64 - 1 > wrow_min) {
#pragma unroll
                for (int mi = 0; mi < 2; mi++) {
                    const int r0 = wrow_min + mi * 16 + qr;
#pragma unroll
                    for (int j = 0; j < 8; j++) {
                        const int c0 = jt * 64 + j * 8 + qc * 2;
                        if (c0     > r0)     sreg[mi][j][0] = -INFINITY;
                        if (c0 + 1 > r0)     sreg[mi][j][1] = -INFINITY;
                        if (c0     > r0 + 8) sreg[mi][j][2] = -INFINITY;
                        if (c0 + 1 > r0 + 8) sreg[mi][j][3] = -INFINITY;
                    }
                }
            }

            // online softmax
#pragma unroll
            for (int mi = 0; mi < 2; mi++) {
                float mt0 = -INFINITY, mt1 = -INFINITY;
#pragma unroll
                for (int j = 0; j < 8; j++) {
                    mt0 = fmaxf(mt0, fmaxf(sreg[mi][j][0], sreg[mi][j][1]));
                    mt1 = fmaxf(mt1, fmaxf(sreg[mi][j][2], sreg[mi][j][3]));
                }
#pragma unroll
                for (int off = 1; off <= 2; off <<= 1) {
                    mt0 = fmaxf(mt0, __shfl_xor_sync(0xffffffffu, mt0, off));
                    mt1 = fmaxf(mt1, __shfl_xor_sync(0xffffffffu, mt1, off));
                }
                const float mn0 = fmaxf(m[mi][0], mt0);
                const float mn1 = fmaxf(m[mi][1], mt1);
                const float al0 = __expf(m[mi][0] - mn0);
                const float al1 = __expf(m[mi][1] - mn1);
                m[mi][0] = mn0; m[mi][1] = mn1;
                float rs0 = 0.0f, rs1 = 0.0f;
#pragma unroll
                for (int j = 0; j < 8; j++) {
                    sreg[mi][j][0] = __expf(sreg[mi][j][0] - mn0);
                    sreg[mi][j][1] = __expf(sreg[mi][j][1] - mn0);
                    sreg[mi][j][2] = __expf(sreg[mi][j][2] - mn1);
                    sreg[mi][j][3] = __expf(sreg[mi][j][3] - mn1);
                    rs0 += sreg[mi][j][0] + sreg[mi][j][1];
                    rs1 += sreg[mi][j][2] + sreg[mi][j][3];
                }
#pragma unroll
                for (int off = 1; off <= 2; off <<= 1) {
                    rs0 += __shfl_xor_sync(0xffffffffu, rs0, off);
                    rs1 += __shfl_xor_sync(0xffffffffu, rs1, off);
                }
                l[mi][0] = l[mi][0] * al0 + rs0;
                l[mi][1] = l[mi][1] * al1 + rs1;
#pragma unroll
                for (int j = 0; j < 8; j++) {
                    o[mi][j][0] *= al0; o[mi][j][1] *= al0;
                    o[mi][j][2] *= al1; o[mi][j][3] *= al1;
                }
            }

            // store P (tf32) to smem
#pragma unroll
            for (int mi = 0; mi < 2; mi++) {
                const int pr = w * 32 + mi * 16 + qr;
#pragma unroll
                for (int j = 0; j < 8; j++) {
                    const int col = j * 8 + qc * 2;
                    uint2 p0 = make_uint2(f2tf32(sreg[mi][j][0]), f2tf32(sreg[mi][j][1]));
                    uint2 p1 = make_uint2(f2tf32(sreg[mi][j][2]), f2tf32(sreg[mi][j][3]));
                    *(uint2*)&Ps[pr * KST + col]       = p0;
                    *(uint2*)&Ps[(pr + 8) * KST + col] = p1;
                }
            }
        }
        __syncthreads();   // P visible (P rows are warp-private, but V reads follow)

        if (!tile_dead) {
            // O += P @ V
#pragma unroll
            for (int ks = 0; ks < 8; ks++) {
                uint32_t pa[2][4];
#pragma unroll
                for (int mi = 0; mi < 2; mi++) {
                    const int pr = w * 32 + mi * 16 + qr;
                    pa[mi][0] = Ps[pr * KST + ks * 8 + qc];
                    pa[mi][1] = Ps[(pr + 8) * KST + ks * 8 + qc];
                    pa[mi][2] = Ps[pr * KST + ks * 8 + 4 + qc];
                    pa[mi][3] = Ps[(pr + 8) * KST + ks * 8 + 4 + qc];
                }
#pragma unroll
                for (int j = 0; j < 8; j++) {
                    const uint32_t b0 = Vs[(ks * 8 + qc) * VST + j * 8 + qr];
                    const uint32_t b1 = Vs[(ks * 8 + 4 + qc) * VST + j * 8 + qr];
                    mma_tf32(o[0][j], pa[0], b0, b1);
                    mma_tf32(o[1][j], pa[1], b0, b1);
                }
            }
        }
    }

    // epilogue: normalize, convert to tf32 bits for the out-proj GEMM
    float* ob = out + ((size_t)(b * LL + qt * 128 + w * 32)) * DD + h * HD;
#pragma unroll
    for (int mi = 0; mi < 2; mi++) {
        const float inv0 = 1.0f / l[mi][0];
        const float inv1 = 1.0f / l[mi][1];
        const size_t r0 = (size_t)(mi * 16 + qr) * DD;
#pragma unroll
        for (int j = 0; j < 8; j++) {
            const int col = j * 8 + qc * 2;
            uint2 v0 = make_uint2(f2tf32(o[mi][j][0] * inv0), f2tf32(o[mi][j][1] * inv0));
            uint2 v1 = make_uint2(f2tf32(o[mi][j][2] * inv1), f2tf32(o[mi][j][3] * inv1));
            *(uint2*)(ob + r0 + col)            = v0;
            *(uint2*)(ob + r0 + 8 * DD + col)   = v1;
        }
    }
}

// ---------------------------------------------------------------------------
extern "C" void kernel_launch(void* const* d_in, const int* in_sizes, int n_in,
                              void* d_out, int out_size)
{
    const float* x    = (const float*)d_in[0];
    const float* Wqkv = (const float*)d_in[1];
    const float* bqkv = (const float*)d_in[2];
    const float* Wout = (const float*)d_in[3];
    const float* bout = (const float*)d_in[4];
    float* outp = (float*)d_out;

    float *qkv = nullptr, *att = nullptr;
    uint32_t *xt = nullptr, *wq = nullptr, *wo = nullptr;
    cudaGetSymbolAddress((void**)&qkv, g_qkv);
    cudaGetSymbolAddress((void**)&att, g_att);
    cudaGetSymbolAddress((void**)&xt, g_xt);
    cudaGetSymbolAddress((void**)&wq, g_wq);
    cudaGetSymbolAddress((void**)&wo, g_wo);

    static bool attr_set = false;
    if (!attr_set) {
        cudaFuncSetAttribute(attn_tf32_kernel,
                             cudaFuncAttributeMaxDynamicSharedMemorySize, SMEM_ATTN);
        attr_set = true;
    }

    const int M = BB * LL;  // 8192

    // tf32 prepass
    {
        int n4 = (M * DD) / 4;
        to_tf32_kernel<<<(n4 + 255) / 256, 256>>>((const float4*)x, (uint4*)xt, n4);
        n4 = (3 * DD * DD) / 4;
        to_tf32_kernel<<<(n4 + 255) / 256, 256>>>((const float4*)Wqkv, (uint4*)wq, n4);
        n4 = (DD * DD) / 4;
        to_tf32_kernel<<<(n4 + 255) / 256, 256>>>((const float4*)Wout, (uint4*)wo, n4);
    }

    // 1) QKV projection (emit tf32 bits, Q pre-scaled by 0.125)
    {
        dim3 grid((3 * DD) / 128, M / 128);
        gemm_tf32<1><<<grid, 128>>>(xt, wq, bqkv, qkv, M, 3 * DD, DD);
    }

    // 2) causal attention (emits tf32 bits)
    {
        dim3 grid(LL / 128, HH, BB);
        attn_tf32_kernel<<<grid, 128, SMEM_ATTN>>>(qkv, att);
    }

    // 3) output projection (fp32 out)
    {
        dim3 grid(DD / 128, M / 128);
        gemm_tf32<0><<<grid, 128>>>((const uint32_t*)att, wo, bout, outp, M, DD, DD);
    }
}

// round 4
// speedup vs baseline: 3.8014x; 1.0378x over previous
#include <cuda_runtime.h>
#include <math.h>
#include <stdint.h>

#define BB 4
#define LL 2048
#define DD 1024
#define HH 16
#define HD 64

// Scratch (device globals)
__device__ float    g_qkv[(size_t)BB * LL * 3 * DD];   // tf32 bits, hd-permuted, Q pre-scaled
__device__ float    g_att[(size_t)BB * LL * DD];       // tf32 bits, D-permuted
__device__ uint32_t g_xt  [(size_t)BB * LL * DD];      // x tf32, K-permuted
__device__ uint32_t g_wq  [(size_t)3 * DD * DD];       // Wqkv tf32, K-permuted + row-permuted
__device__ uint32_t g_wo  [(size_t)DD * DD];           // Wout tf32, K-permuted
__device__ float    g_bq  [3 * DD];                    // qkv bias, permuted

__device__ __forceinline__ uint32_t f2tf32(float x) {
    uint32_t r;
    asm("cvt.rna.tf32.f32 %0, %1;" : "=r"(r) : "f"(x));
    return r;
}
__device__ __host__ __forceinline__ int pos8(int i) {
    int g = i & 7;
    return (i & ~7) | ((g < 4) ? (g << 1) : (((g - 4) << 1) | 1));
}

__device__ __forceinline__ void cp_async16(uint32_t smem_addr, const void* gptr) {
    asm volatile("cp.async.cg.shared.global [%0], [%1], 16;\n"
                 :: "r"(smem_addr), "l"(gptr));
}
__device__ __forceinline__ void cp_commit() {
    asm volatile("cp.async.commit_group;\n" ::: "memory");
}
template <int N>
__device__ __forceinline__ void cp_wait() {
    asm volatile("cp.async.wait_group %0;\n" :: "n"(N) : "memory");
}

// m16n8k8 tf32 mma.
__device__ __forceinline__ void mma_tf32(float* d, const uint32_t* a,
                                         uint32_t b0, uint32_t b1) {
    asm volatile(
        "mma.sync.aligned.m16n8k8.row.col.f32.tf32.tf32.f32 "
        "{%0,%1,%2,%3}, {%4,%5,%6,%7}, {%8,%9}, {%0,%1,%2,%3};\n"
        : "+f"(d[0]), "+f"(d[1]), "+f"(d[2]), "+f"(d[3])
        : "r"(a[0]), "r"(a[1]), "r"(a[2]), "r"(a[3]), "r"(b0), "r"(b1));
}

// ---------------------------------------------------------------------------
// Prepass: fp32 -> tf32 bits, K permuted within 8-groups; optional row perm.
// One thread per 8-element K group.
// ---------------------------------------------------------------------------
template <int PERM_ROWS>
__global__ void perm_tf32_kernel(const float* __restrict__ in,
                                 uint32_t* __restrict__ out, int rows, int cols) {
    int gid = blockIdx.x * blockDim.x + threadIdx.x;
    const int gpr = cols >> 3;
    if (gid >= rows * gpr) return;
    const int r = gid / gpr;
    const int gk = gid - r * gpr;
    const float4 v0 = *(const float4*)(in + (size_t)r * cols + gk * 8);
    const float4 v1 = *(const float4*)(in + (size_t)r * cols + gk * 8 + 4);
    const int rp = PERM_ROWS ? pos8(r) : r;
    uint32_t* o = out + (size_t)rp * cols + gk * 8;
    o[0] = f2tf32(v0.x); o[2] = f2tf32(v0.y); o[4] = f2tf32(v0.z); o[6] = f2tf32(v0.w);
    o[1] = f2tf32(v1.x); o[3] = f2tf32(v1.y); o[5] = f2tf32(v1.z); o[7] = f2tf32(v1.w);
}

__global__ void perm_bias_kernel(const float* __restrict__ in,
                                 float* __restrict__ out, int n) {
    int i = blockIdx.x * blockDim.x + threadIdx.x;
    if (i < n) out[pos8(i)] = in[i];
}

// ---------------------------------------------------------------------------
// tf32 GEMM, C = A @ W^T + bias. A:[M,K], W:[N,K], tf32 bits, K pre-permuted.
// Block 128x128, kTile 16, 4 warps (2x2), warp 64x64. 3-stage cp.async,
// one __syncthreads per kTile. Smem stride 24 words: all LDS.64 conflict-free.
// MODE 0: fp32 out. MODE 1: tf32-bits out, cols<DD scaled 0.125, bias pre-permuted.
// ---------------------------------------------------------------------------
#define GST 24
#define GBUF (128 * GST)
#define SMEM_GEMM (3 * GBUF * 2 * 4)

template <int MODE>
__global__ __launch_bounds__(128) void gemm_tf32(
    const uint32_t* __restrict__ A, const uint32_t* __restrict__ W,
    const float* __restrict__ bias, float* __restrict__ C,
    int M, int N, int K)
{
    extern __shared__ uint32_t gsm[];   // As[3][GBUF] | Ws[3][GBUF]

    const int tid = threadIdx.x;
    const int lane = tid & 31;
    const int ww = tid >> 5;
    const int wr = ww >> 1;
    const int wc = ww & 1;
    const int qr = lane >> 2;
    const int qc = lane & 3;
    const int bm = blockIdx.y * 128;
    const int bn = blockIdx.x * 128;

    float acc[4][8][4];
#pragma unroll
    for (int i = 0; i < 4; i++)
#pragma unroll
        for (int j = 0; j < 8; j++)
#pragma unroll
            for (int c = 0; c < 4; c++) acc[i][j][c] = 0.0f;

    const uint32_t sm_base = (uint32_t)__cvta_generic_to_shared(gsm);
    const int nkt = K / 16;

    auto stage = [&](int kt_idx, int s) {
#pragma unroll
        for (int i = 0; i < 8; i++) {
            const int q = i * 128 + tid;
            const int r = (q & 511) >> 2;
            const int c = q & 3;
            if (q < 512) {
                cp_async16(sm_base + (uint32_t)((s * GBUF + r * GST + c * 4) * 4),
                           A + (size_t)(bm + r) * K + kt_idx * 16 + c * 4);
            } else {
                cp_async16(sm_base + (uint32_t)((3 * GBUF + s * GBUF + r * GST + c * 4) * 4),
                           W + (size_t)(bn + r) * K + kt_idx * 16 + c * 4);
            }
        }
        cp_commit();
    };

    stage(0, 0);
    stage(1, 1);

    int s = 0;
    for (int kt = 0; kt < nkt; kt++) {
        if (kt + 1 < nkt) cp_wait<1>();
        else              cp_wait<0>();
        __syncthreads();
        if (kt + 2 < nkt) {
            int s2 = s + 2; if (s2 >= 3) s2 -= 3;
            stage(kt + 2, s2);
        }

        const uint32_t* As = gsm + s * GBUF;
        const uint32_t* Ws = gsm + 3 * GBUF + s * GBUF;

#pragma unroll
        for (int ks = 0; ks < 16; ks += 8) {
            uint32_t aa[4][4], bb[8][2];
#pragma unroll
            for (int mi = 0; mi < 4; mi++) {
                const int m = wr * 64 + mi * 16 + qr;
                const uint2 u0 = *(const uint2*)&As[m * GST + ks + 2 * qc];
                const uint2 u1 = *(const uint2*)&As[(m + 8) * GST + ks + 2 * qc];
                aa[mi][0] = u0.x; aa[mi][1] = u1.x;
                aa[mi][2] = u0.y; aa[mi][3] = u1.y;
            }
#pragma unroll
            for (int ni = 0; ni < 8; ni++) {
                const int n = wc * 64 + ni * 8 + qr;
                const uint2 v = *(const uint2*)&Ws[n * GST + ks + 2 * qc];
                bb[ni][0] = v.x; bb[ni][1] = v.y;
            }
#pragma unroll
            for (int mi = 0; mi < 4; mi++)
#pragma unroll
                for (int ni = 0; ni < 8; ni++)
                    mma_tf32(acc[mi][ni], aa[mi], bb[ni][0], bb[ni][1]);
        }
        s++; if (s == 3) s = 0;
    }

#pragma unroll
    for (int mi = 0; mi < 4; mi++) {
        const int row = bm + wr * 64 + mi * 16 + qr;
#pragma unroll
        for (int ni = 0; ni < 8; ni++) {
            const int col = bn + wc * 64 + ni * 8 + qc * 2;
            const float b0 = bias[col], b1 = bias[col + 1];
            float* d = acc[mi][ni];
            float v00 = d[0] + b0, v01 = d[1] + b1;
            float v10 = d[2] + b0, v11 = d[3] + b1;
            if (MODE == 1) {
                const float sc = (col < DD) ? 0.125f : 1.0f;
                v00 = __uint_as_float(f2tf32(v00 * sc));
                v01 = __uint_as_float(f2tf32(v01 * sc));
                v10 = __uint_as_float(f2tf32(v10 * sc));
                v11 = __uint_as_float(f2tf32(v11 * sc));
            }
            *(float2*)(C + (size_t)row * N + col)       = make_float2(v00, v01);
            *(float2*)(C + (size_t)(row + 8) * N + col) = make_float2(v10, v11);
        }
    }
}

// ---------------------------------------------------------------------------
// Causal flash attention, tf32 mma. Grid (L/128, H, B) qt reversed, 4 warps.
// qkv is tf32 bits with hd permuted within 8-groups (so K-fragments are LDS.64)
// and Q pre-scaled. K stride 72, V stride 72, P stride 68 (all conflict-free).
// ---------------------------------------------------------------------------
#define KST 72
#define VST 72
#define PST 68
#define K_WORDS (64 * KST)
#define V_WORDS (64 * VST)
#define OFF_K0 0
#define OFF_V0 (2 * K_WORDS)
#define OFF_P  (2 * K_WORDS + 2 * V_WORDS)
#define SMEM_ATTN ((2 * K_WORDS + 2 * V_WORDS + 128 * PST) * 4)

__global__ __launch_bounds__(128) void attn_tf32_kernel(
    const float* __restrict__ qkvf, float* __restrict__ out)
{
    extern __shared__ uint32_t sm[];
    const uint32_t* qkv = (const uint32_t*)qkvf;

    const int qt = gridDim.x - 1 - blockIdx.x;
    const int h  = blockIdx.y;
    const int b  = blockIdx.z;

    const int tid = threadIdx.x;
    const int lane = tid & 31;
    const int w = tid >> 5;
    const int qr = lane >> 2;
    const int qc = lane & 3;

    const size_t rs = 3 * DD;
    const uint32_t sm_base = (uint32_t)__cvta_generic_to_shared(sm);

    // Q fragments (hd-permuted globally: logical {qc, qc+4} at {2qc, 2qc+1})
    uint32_t qa[2][8][4];
    const uint32_t* qb = qkv + ((size_t)(b * LL + qt * 128 + w * 32)) * rs + h * HD;
#pragma unroll
    for (int mi = 0; mi < 2; mi++)
#pragma unroll
        for (int ks = 0; ks < 8; ks++) {
            const size_t r0 = (size_t)(mi * 16 + qr) * rs;
            const uint2 u0 = *(const uint2*)(qb + r0 + ks * 8 + 2 * qc);
            const uint2 u1 = *(const uint2*)(qb + r0 + 8 * rs + ks * 8 + 2 * qc);
            qa[mi][ks][0] = u0.x; qa[mi][ks][1] = u1.x;
            qa[mi][ks][2] = u0.y; qa[mi][ks][3] = u1.y;
        }

    float o[2][8][4];
    float m[2][2], l[2][2];
#pragma unroll
    for (int mi = 0; mi < 2; mi++) {
        m[mi][0] = m[mi][1] = -INFINITY;
        l[mi][0] = l[mi][1] = 0.0f;
#pragma unroll
        for (int j = 0; j < 8; j++)
#pragma unroll
            for (int c = 0; c < 4; c++) o[mi][j][c] = 0.0f;
    }

    const int jmax = 2 * qt + 1;

    auto stage = [&](int jt, int s) {
        const uint32_t* kg = qkv + ((size_t)(b * LL + jt * 64)) * rs + DD + h * HD;
        const uint32_t* vg = kg + DD;
#pragma unroll
        for (int i = 0; i < 8; i++) {
            const int q = i * 128 + tid;
            const int r = q >> 4, c = q & 15;
            cp_async16(sm_base + (uint32_t)((OFF_K0 + s * K_WORDS + r * KST + c * 4) * 4),
                       kg + (size_t)r * rs + c * 4);
        }
#pragma unroll
        for (int i = 0; i < 8; i++) {
            const int q = i * 128 + tid;
            const int r = q >> 4, c = q & 15;
            cp_async16(sm_base + (uint32_t)((OFF_V0 + s * V_WORDS + r * VST + c * 4) * 4),
                       vg + (size_t)r * rs + c * 4);
        }
        cp_commit();
    };

    stage(0, 0);

    for (int jt = 0; jt <= jmax; jt++) {
        const int s = jt & 1;
        __syncthreads();
        if (jt + 1 <= jmax) { stage(jt + 1, s ^ 1); cp_wait<1>(); }
        else                { cp_wait<0>(); }
        __syncthreads();

        const uint32_t* Ks = sm + OFF_K0 + s * K_WORDS;
        const uint32_t* Vs = sm + OFF_V0 + s * V_WORDS;
        uint32_t* Ps = sm + OFF_P;

        const int wrow_min = qt * 128 + w * 32;
        const bool tile_dead = (jt * 64) > (wrow_min + 31);

        if (!tile_dead) {
            float sreg[2][8][4];
#pragma unroll
            for (int mi = 0; mi < 2; mi++)
#pragma unroll
                for (int j = 0; j < 8; j++)
#pragma unroll
                    for (int c = 0; c < 4; c++) sreg[mi][j][c] = 0.0f;

#pragma unroll
            for (int ks = 0; ks < 8; ks++) {
#pragma unroll
                for (int j = 0; j < 8; j++) {
                    const uint2 kk = *(const uint2*)&Ks[(j * 8 + qr) * KST + ks * 8 + 2 * qc];
                    mma_tf32(sreg[0][j], qa[0][ks], kk.x, kk.y);
                    mma_tf32(sreg[1][j], qa[1][ks], kk.x, kk.y);
                }
            }

            if ((jt + 1) * 64 - 1 > wrow_min) {
#pragma unroll
                for (int mi = 0; mi < 2; mi++) {
                    const int r0 = wrow_min + mi * 16 + qr;
#pragma unroll
                    for (int j = 0; j < 8; j++) {
                        const int c0 = jt * 64 + j * 8 + qc * 2;
                        if (c0     > r0)     sreg[mi][j][0] = -INFINITY;
                        if (c0 + 1 > r0)     sreg[mi][j][1] = -INFINITY;
                        if (c0     > r0 + 8) sreg[mi][j][2] = -INFINITY;
                        if (c0 + 1 > r0 + 8) sreg[mi][j][3] = -INFINITY;
                    }
                }
            }

#pragma unroll
            for (int mi = 0; mi < 2; mi++) {
                float mt0 = -INFINITY, mt1 = -INFINITY;
#pragma unroll
                for (int j = 0; j < 8; j++) {
                    mt0 = fmaxf(mt0, fmaxf(sreg[mi][j][0], sreg[mi][j][1]));
                    mt1 = fmaxf(mt1, fmaxf(sreg[mi][j][2], sreg[mi][j][3]));
                }
#pragma unroll
                for (int off = 1; off <= 2; off <<= 1) {
                    mt0 = fmaxf(mt0, __shfl_xor_sync(0xffffffffu, mt0, off));
                    mt1 = fmaxf(mt1, __shfl_xor_sync(0xffffffffu, mt1, off));
                }
                const float mn0 = fmaxf(m[mi][0], mt0);
                const float mn1 = fmaxf(m[mi][1], mt1);
                const float al0 = __expf(m[mi][0] - mn0);
                const float al1 = __expf(m[mi][1] - mn1);
                m[mi][0] = mn0; m[mi][1] = mn1;
                float rs0 = 0.0f, rs1 = 0.0f;
#pragma unroll
                for (int j = 0; j < 8; j++) {
                    sreg[mi][j][0] = __expf(sreg[mi][j][0] - mn0);
                    sreg[mi][j][1] = __expf(sreg[mi][j][1] - mn0);
                    sreg[mi][j][2] = __expf(sreg[mi][j][2] - mn1);
                    sreg[mi][j][3] = __expf(sreg[mi][j][3] - mn1);
                    rs0 += sreg[mi][j][0] + sreg[mi][j][1];
                    rs1 += sreg[mi][j][2] + sreg[mi][j][3];
                }
#pragma unroll
                for (int off = 1; off <= 2; off <<= 1) {
                    rs0 += __shfl_xor_sync(0xffffffffu, rs0, off);
                    rs1 += __shfl_xor_sync(0xffffffffu, rs1, off);
                }
                l[mi][0] = l[mi][0] * al0 + rs0;
                l[mi][1] = l[mi][1] * al1 + rs1;
#pragma unroll
                for (int j = 0; j < 8; j++) {
                    o[mi][j][0] *= al0; o[mi][j][1] *= al0;
                    o[mi][j][2] *= al1; o[mi][j][3] *= al1;
                }
            }

#pragma unroll
            for (int mi = 0; mi < 2; mi++) {
                const int pr = w * 32 + mi * 16 + qr;
#pragma unroll
                for (int j = 0; j < 8; j++) {
                    const int col = j * 8 + qc * 2;
                    uint2 p0 = make_uint2(f2tf32(sreg[mi][j][0]), f2tf32(sreg[mi][j][1]));
                    uint2 p1 = make_uint2(f2tf32(sreg[mi][j][2]), f2tf32(sreg[mi][j][3]));
                    *(uint2*)&Ps[pr * PST + col]       = p0;
                    *(uint2*)&Ps[(pr + 8) * PST + col] = p1;
                }
            }
        }
        __syncthreads();

        if (!tile_dead) {
#pragma unroll
            for (int ks = 0; ks < 8; ks++) {
                uint32_t pa[2][4];
#pragma unroll
                for (int mi = 0; mi < 2; mi++) {
                    const int pr = w * 32 + mi * 16 + qr;
                    pa[mi][0] = Ps[pr * PST + ks * 8 + qc];
                    pa[mi][1] = Ps[(pr + 8) * PST + ks * 8 + qc];
                    pa[mi][2] = Ps[pr * PST + ks * 8 + 4 + qc];
                    pa[mi][3] = Ps[(pr + 8) * PST + ks * 8 + 4 + qc];
                }
#pragma unroll
                for (int j = 0; j < 8; j++) {
                    const uint32_t b0 = Vs[(ks * 8 + qc) * VST + j * 8 + qr];
                    const uint32_t b1 = Vs[(ks * 8 + 4 + qc) * VST + j * 8 + qr];
                    mma_tf32(o[0][j], pa[0], b0, b1);
                    mma_tf32(o[1][j], pa[1], b0, b1);
                }
            }
        }
    }

    // epilogue: V cols were hd-permuted, so writing at face positions yields
    // exactly the K-permuted layout gemm0 expects.
    float* ob = out + ((size_t)(b * LL + qt * 128 + w * 32)) * DD + h * HD;
#pragma unroll
    for (int mi = 0; mi < 2; mi++) {
        const float inv0 = 1.0f / l[mi][0];
        const float inv1 = 1.0f / l[mi][1];
        const size_t r0 = (size_t)(mi * 16 + qr) * DD;
#pragma unroll
        for (int j = 0; j < 8; j++) {
            const int col = j * 8 + qc * 2;
            uint2 v0 = make_uint2(f2tf32(o[mi][j][0] * inv0), f2tf32(o[mi][j][1] * inv0));
            uint2 v1 = make_uint2(f2tf32(o[mi][j][2] * inv1), f2tf32(o[mi][j][3] * inv1));
            *(uint2*)(ob + r0 + col)          = v0;
            *(uint2*)(ob + r0 + 8 * DD + col) = v1;
        }
    }
}

// ---------------------------------------------------------------------------
extern "C" void kernel_launch(void* const* d_in, const int* in_sizes, int n_in,
                              void* d_out, int out_size)
{
    const float* x    = (const float*)d_in[0];
    const float* Wqkv = (const float*)d_in[1];
    const float* bqkv = (const float*)d_in[2];
    const float* Wout = (const float*)d_in[3];
    const float* bout = (const float*)d_in[4];
    float* outp = (float*)d_out;

    float *qkv = nullptr, *att = nullptr, *bq = nullptr;
    uint32_t *xt = nullptr, *wq = nullptr, *wo = nullptr;
    cudaGetSymbolAddress((void**)&qkv, g_qkv);
    cudaGetSymbolAddress((void**)&att, g_att);
    cudaGetSymbolAddress((void**)&xt, g_xt);
    cudaGetSymbolAddress((void**)&wq, g_wq);
    cudaGetSymbolAddress((void**)&wo, g_wo);
    cudaGetSymbolAddress((void**)&bq, g_bq);

    static bool attr_set = false;
    if (!attr_set) {
        cudaFuncSetAttribute(attn_tf32_kernel,
                             cudaFuncAttributeMaxDynamicSharedMemorySize, SMEM_ATTN);
        cudaFuncSetAttribute(gemm_tf32<0>,
                             cudaFuncAttributeMaxDynamicSharedMemorySize, SMEM_GEMM);
        cudaFuncSetAttribute(gemm_tf32<1>,
                             cudaFuncAttributeMaxDynamicSharedMemorySize, SMEM_GEMM);
        attr_set = true;
    }

    const int M = BB * LL;  // 8192

    // prepass: tf32 + K-permutation (+ row perm for Wqkv), bias perm
    {
        int ng = (M * DD) / 8;
        perm_tf32_kernel<0><<<(ng + 255) / 256, 256>>>(x, xt, M, DD);
        ng = (3 * DD * DD) / 8;
        perm_tf32_kernel<1><<<(ng + 255) / 256, 256>>>(Wqkv, wq, 3 * DD, DD);
        ng = (DD * DD) / 8;
        perm_tf32_kernel<0><<<(ng + 255) / 256, 256>>>(Wout, wo, DD, DD);
        perm_bias_kernel<<<12, 256>>>(bqkv, bq, 3 * DD);
    }

    // 1) QKV projection (tf32 bits out, Q pre-scaled, hd-permuted layout)
    {
        dim3 grid((3 * DD) / 128, M / 128);
        gemm_tf32<1><<<grid, 128, SMEM_GEMM>>>(xt, wq, bq, qkv, M, 3 * DD, DD);
    }

    // 2) causal attention
    {
        dim3 grid(LL / 128, HH, BB);
        attn_tf32_kernel<<<grid, 128, SMEM_ATTN>>>(qkv, att);
    }

    // 3) output projection (fp32 out, unpermuted)
    {
        dim3 grid(DD / 128, M / 128);
        gemm_tf32<0><<<grid, 128, SMEM_GEMM>>>((const uint32_t*)att, wo, bout, outp, M, DD, DD);
    }
}

// round 6
// speedup vs baseline: 4.0382x; 1.0623x over previous
#include <cuda_runtime.h>
#include <math.h>
#include <stdint.h>

#define BB 4
#define LL 2048
#define DD 1024
#define HH 16
#define HD 64

// Q prescale: 1/sqrt(64) * log2(e), so softmax can use exp2 directly.
#define QSCALE 0.1803368801111204f

// Scratch (device globals)
__device__ float    g_qkv[(size_t)BB * LL * 3 * DD];   // tf32 bits, hd-permuted, Q pre-scaled
__device__ float    g_att[(size_t)BB * LL * DD];       // tf32 bits, D-permuted
__device__ uint32_t g_xt  [(size_t)BB * LL * DD];      // x tf32, K-permuted
__device__ uint32_t g_wq  [(size_t)3 * DD * DD];       // Wqkv tf32, K-permuted + row-permuted
__device__ uint32_t g_wo  [(size_t)DD * DD];           // Wout tf32, K-permuted
__device__ float    g_bq  [3 * DD];                    // qkv bias, permuted

__device__ __forceinline__ uint32_t f2tf32(float x) {
    uint32_t r;
    asm("cvt.rna.tf32.f32 %0, %1;" : "=r"(r) : "f"(x));
    return r;
}
__device__ __host__ __forceinline__ int pos8(int i) {
    int g = i & 7;
    return (i & ~7) | ((g < 4) ? (g << 1) : (((g - 4) << 1) | 1));
}

__device__ __forceinline__ void cp_async16(uint32_t smem_addr, const void* gptr) {
    asm volatile("cp.async.cg.shared.global [%0], [%1], 16;\n"
                 :: "r"(smem_addr), "l"(gptr));
}
__device__ __forceinline__ void cp_commit() {
    asm volatile("cp.async.commit_group;\n" ::: "memory");
}
template <int N>
__device__ __forceinline__ void cp_wait() {
    asm volatile("cp.async.wait_group %0;\n" :: "n"(N) : "memory");
}

// m16n8k8 tf32 mma. A frag: a0=(r,qc) a1=(r+8,qc) a2=(r,qc+4) a3=(r+8,qc+4)
// B frag: b0=(k=qc,n=qr) b1=(k=qc+4,n=qr). C: c0=(r,2qc) c1=(r,2qc+1) c2/c3 = +8 rows.
__device__ __forceinline__ void mma_tf32(float* d, const uint32_t* a,
                                         uint32_t b0, uint32_t b1) {
    asm volatile(
        "mma.sync.aligned.m16n8k8.row.col.f32.tf32.tf32.f32 "
        "{%0,%1,%2,%3}, {%4,%5,%6,%7}, {%8,%9}, {%0,%1,%2,%3};\n"
        : "+f"(d[0]), "+f"(d[1]), "+f"(d[2]), "+f"(d[3])
        : "r"(a[0]), "r"(a[1]), "r"(a[2]), "r"(a[3]), "r"(b0), "r"(b1));
}

// ---------------------------------------------------------------------------
// Prepass: fp32 -> tf32 bits, K permuted within 8-groups; optional row perm.
// ---------------------------------------------------------------------------
template <int PERM_ROWS>
__global__ void perm_tf32_kernel(const float* __restrict__ in,
                                 uint32_t* __restrict__ out, int rows, int cols) {
    int gid = blockIdx.x * blockDim.x + threadIdx.x;
    const int gpr = cols >> 3;
    if (gid >= rows * gpr) return;
    const int r = gid / gpr;
    const int gk = gid - r * gpr;
    const float4 v0 = *(const float4*)(in + (size_t)r * cols + gk * 8);
    const float4 v1 = *(const float4*)(in + (size_t)r * cols + gk * 8 + 4);
    const int rp = PERM_ROWS ? pos8(r) : r;
    uint32_t* o = out + (size_t)rp * cols + gk * 8;
    o[0] = f2tf32(v0.x); o[2] = f2tf32(v0.y); o[4] = f2tf32(v0.z); o[6] = f2tf32(v0.w);
    o[1] = f2tf32(v1.x); o[3] = f2tf32(v1.y); o[5] = f2tf32(v1.z); o[7] = f2tf32(v1.w);
}

__global__ void perm_bias_kernel(const float* __restrict__ in,
                                 float* __restrict__ out, int n) {
    int i = blockIdx.x * blockDim.x + threadIdx.x;
    if (i < n) out[pos8(i)] = in[i];
}

// ---------------------------------------------------------------------------
// tf32 GEMM (mma.sync), C = A @ W^T + bias. K pre-permuted on both operands.
// Block 128x128, kTile 16, 4 warps (2x2), warp 64x64. 3-stage cp.async,
// one __syncthreads per kTile. Smem stride 24 words: all LDS.64 conflict-free.
// MODE 0: fp32 out. MODE 1: tf32 bits out, cols<DD scaled by QSCALE.
// ---------------------------------------------------------------------------
#define GST 24
#define GBUF (128 * GST)
#define SMEM_GEMM (3 * GBUF * 2 * 4)

template <int MODE>
__global__ __launch_bounds__(128) void gemm_tf32(
    const uint32_t* __restrict__ A, const uint32_t* __restrict__ W,
    const float* __restrict__ bias, float* __restrict__ C,
    int M, int N, int K)
{
    extern __shared__ uint32_t gsm[];   // As[3][GBUF] | Ws[3][GBUF]

    const int tid = threadIdx.x;
    const int lane = tid & 31;
    const int ww = tid >> 5;
    const int wr = ww >> 1;
    const int wc = ww & 1;
    const int qr = lane >> 2;
    const int qc = lane & 3;
    const int bm = blockIdx.y * 128;
    const int bn = blockIdx.x * 128;

    float acc[4][8][4];
#pragma unroll
    for (int i = 0; i < 4; i++)
#pragma unroll
        for (int j = 0; j < 8; j++)
#pragma unroll
            for (int c = 0; c < 4; c++) acc[i][j][c] = 0.0f;

    const uint32_t sm_base = (uint32_t)__cvta_generic_to_shared(gsm);
    const int nkt = K / 16;

    auto stage = [&](int kt_idx, int s) {
#pragma unroll
        for (int i = 0; i < 8; i++) {
            const int q = i * 128 + tid;
            const int r = (q & 511) >> 2;
            const int c = q & 3;
            if (q < 512) {
                cp_async16(sm_base + (uint32_t)((s * GBUF + r * GST + c * 4) * 4),
                           A + (size_t)(bm + r) * K + kt_idx * 16 + c * 4);
            } else {
                cp_async16(sm_base + (uint32_t)((3 * GBUF + s * GBUF + r * GST + c * 4) * 4),
                           W + (size_t)(bn + r) * K + kt_idx * 16 + c * 4);
            }
        }
        cp_commit();
    };

    stage(0, 0);
    stage(1, 1);

    int s = 0;
    for (int kt = 0; kt < nkt; kt++) {
        if (kt + 1 < nkt) cp_wait<1>();
        else              cp_wait<0>();
        __syncthreads();
        if (kt + 2 < nkt) {
            int s2 = s + 2; if (s2 >= 3) s2 -= 3;
            stage(kt + 2, s2);
        }

        const uint32_t* As = gsm + s * GBUF;
        const uint32_t* Ws = gsm + 3 * GBUF + s * GBUF;

#pragma unroll
        for (int ks = 0; ks < 16; ks += 8) {
            uint32_t aa[4][4], bb[8][2];
#pragma unroll
            for (int mi = 0; mi < 4; mi++) {
                const int m = wr * 64 + mi * 16 + qr;
                const uint2 u0 = *(const uint2*)&As[m * GST + ks + 2 * qc];
                const uint2 u1 = *(const uint2*)&As[(m + 8) * GST + ks + 2 * qc];
                aa[mi][0] = u0.x; aa[mi][1] = u1.x;
                aa[mi][2] = u0.y; aa[mi][3] = u1.y;
            }
#pragma unroll
            for (int ni = 0; ni < 8; ni++) {
                const int n = wc * 64 + ni * 8 + qr;
                const uint2 v = *(const uint2*)&Ws[n * GST + ks + 2 * qc];
                bb[ni][0] = v.x; bb[ni][1] = v.y;
            }
#pragma unroll
            for (int mi = 0; mi < 4; mi++)
#pragma unroll
                for (int ni = 0; ni < 8; ni++)
                    mma_tf32(acc[mi][ni], aa[mi], bb[ni][0], bb[ni][1]);
        }
        s++; if (s == 3) s = 0;
    }

#pragma unroll
    for (int mi = 0; mi < 4; mi++) {
        const int row = bm + wr * 64 + mi * 16 + qr;
#pragma unroll
        for (int ni = 0; ni < 8; ni++) {
            const int col = bn + wc * 64 + ni * 8 + qc * 2;
            const float b0 = bias[col], b1 = bias[col + 1];
            float* d = acc[mi][ni];
            float v00 = d[0] + b0, v01 = d[1] + b1;
            float v10 = d[2] + b0, v11 = d[3] + b1;
            if (MODE == 1) {
                const float sc = (col < DD) ? QSCALE : 1.0f;
                v00 = __uint_as_float(f2tf32(v00 * sc));
                v01 = __uint_as_float(f2tf32(v01 * sc));
                v10 = __uint_as_float(f2tf32(v10 * sc));
                v11 = __uint_as_float(f2tf32(v11 * sc));
            }
            *(float2*)(C + (size_t)row * N + col)       = make_float2(v00, v01);
            *(float2*)(C + (size_t)(row + 8) * N + col) = make_float2(v10, v11);
        }
    }
}

// ---------------------------------------------------------------------------
// Causal flash attention, tf32 mma. Grid (L/128, H, B) qt reversed, 4 warps.
// qkv is tf32 bits with hd permuted within 8-groups, Q pre-scaled by QSCALE.
// NEW vs R4: P stays in registers; V seq rows are stored pos8-inverse-permuted
// in smem so the post-softmax S fragments are directly valid PV A-fragments.
// Only 2 __syncthreads per KV tile. Softmax in exp2 domain.
// ---------------------------------------------------------------------------
#define KST 72
#define VST 72
#define K_WORDS (64 * KST)
#define V_WORDS (64 * VST)
#define OFF_K0 0
#define OFF_V0 (2 * K_WORDS)
#define SMEM_ATTN ((2 * K_WORDS + 2 * V_WORDS) * 4)

__global__ __launch_bounds__(128) void attn_tf32_kernel(
    const float* __restrict__ qkvf, float* __restrict__ out)
{
    extern __shared__ uint32_t sm[];
    const uint32_t* qkv = (const uint32_t*)qkvf;

    const int qt = gridDim.x - 1 - blockIdx.x;
    const int h  = blockIdx.y;
    const int b  = blockIdx.z;

    const int tid = threadIdx.x;
    const int lane = tid & 31;
    const int w = tid >> 5;
    const int qr = lane >> 2;
    const int qc = lane & 3;

    const size_t rs = 3 * DD;
    const uint32_t sm_base = (uint32_t)__cvta_generic_to_shared(sm);

    uint32_t qa[2][8][4];
    const uint32_t* qb = qkv + ((size_t)(b * LL + qt * 128 + w * 32)) * rs + h * HD;
#pragma unroll
    for (int mi = 0; mi < 2; mi++)
#pragma unroll
        for (int ks = 0; ks < 8; ks++) {
            const size_t r0 = (size_t)(mi * 16 + qr) * rs;
            const uint2 u0 = *(const uint2*)(qb + r0 + ks * 8 + 2 * qc);
            const uint2 u1 = *(const uint2*)(qb + r0 + 8 * rs + ks * 8 + 2 * qc);
            qa[mi][ks][0] = u0.x; qa[mi][ks][1] = u1.x;
            qa[mi][ks][2] = u0.y; qa[mi][ks][3] = u1.y;
        }

    float o[2][8][4];
    float m[2][2], l[2][2];
#pragma unroll
    for (int mi = 0; mi < 2; mi++) {
        m[mi][0] = m[mi][1] = -INFINITY;
        l[mi][0] = l[mi][1] = 0.0f;
#pragma unroll
        for (int j = 0; j < 8; j++)
#pragma unroll
            for (int c = 0; c < 4; c++) o[mi][j][c] = 0.0f;
    }

    const int jmax = 2 * qt + 1;

    auto stage = [&](int jt, int s) {
        const uint32_t* kg = qkv + ((size_t)(b * LL + jt * 64)) * rs + DD + h * HD;
        const uint32_t* vg = kg + DD;
#pragma unroll
        for (int i = 0; i < 8; i++) {
            const int q = i * 128 + tid;
            const int r = q >> 4, c = q & 15;
            cp_async16(sm_base + (uint32_t)((OFF_K0 + s * K_WORDS + r * KST + c * 4) * 4),
                       kg + (size_t)r * rs + c * 4);
        }
#pragma unroll
        for (int i = 0; i < 8; i++) {
            const int q = i * 128 + tid;
            const int r = q >> 4, c = q & 15;
            // seq-row permutation: even g -> g/2, odd g -> g/2 + 4 (pos8 inverse)
            const int g = r & 7;
            const int pr = (r & ~7) | ((g & 1) ? ((g >> 1) + 4) : (g >> 1));
            cp_async16(sm_base + (uint32_t)((OFF_V0 + s * V_WORDS + pr * VST + c * 4) * 4),
                       vg + (size_t)r * rs + c * 4);
        }
        cp_commit();
    };

    stage(0, 0);

    for (int jt = 0; jt <= jmax; jt++) {
        const int s = jt & 1;
        __syncthreads();   // all warps done reading buffer s^1 (iter jt-1)
        if (jt + 1 <= jmax) { stage(jt + 1, s ^ 1); cp_wait<1>(); }
        else                { cp_wait<0>(); }
        __syncthreads();

        const uint32_t* Ks = sm + OFF_K0 + s * K_WORDS;
        const uint32_t* Vs = sm + OFF_V0 + s * V_WORDS;

        const int wrow_min = qt * 128 + w * 32;
        const bool tile_dead = (jt * 64) > (wrow_min + 31);

        if (!tile_dead) {
            // S = Q K^T
            float sreg[2][8][4];
#pragma unroll
            for (int mi = 0; mi < 2; mi++)
#pragma unroll
                for (int j = 0; j < 8; j++)
#pragma unroll
                    for (int c = 0; c < 4; c++) sreg[mi][j][c] = 0.0f;

#pragma unroll
            for (int ks = 0; ks < 8; ks++) {
#pragma unroll
                for (int j = 0; j < 8; j++) {
                    const uint2 kk = *(const uint2*)&Ks[(j * 8 + qr) * KST + ks * 8 + 2 * qc];
                    mma_tf32(sreg[0][j], qa[0][ks], kk.x, kk.y);
                    mma_tf32(sreg[1][j], qa[1][ks], kk.x, kk.y);
                }
            }

            // causal mask
            if ((jt + 1) * 64 - 1 > wrow_min) {
#pragma unroll
                for (int mi = 0; mi < 2; mi++) {
                    const int r0 = wrow_min + mi * 16 + qr;
#pragma unroll
                    for (int j = 0; j < 8; j++) {
                        const int c0 = jt * 64 + j * 8 + qc * 2;
                        if (c0     > r0)     sreg[mi][j][0] = -INFINITY;
                        if (c0 + 1 > r0)     sreg[mi][j][1] = -INFINITY;
                        if (c0     > r0 + 8) sreg[mi][j][2] = -INFINITY;
                        if (c0 + 1 > r0 + 8) sreg[mi][j][3] = -INFINITY;
                    }
                }
            }

            // online softmax (base-2; log2e folded into Q prescale)
#pragma unroll
            for (int mi = 0; mi < 2; mi++) {
                float mt0 = -INFINITY, mt1 = -INFINITY;
#pragma unroll
                for (int j = 0; j < 8; j++) {
                    mt0 = fmaxf(mt0, fmaxf(sreg[mi][j][0], sreg[mi][j][1]));
                    mt1 = fmaxf(mt1, fmaxf(sreg[mi][j][2], sreg[mi][j][3]));
                }
#pragma unroll
                for (int off = 1; off <= 2; off <<= 1) {
                    mt0 = fmaxf(mt0, __shfl_xor_sync(0xffffffffu, mt0, off));
                    mt1 = fmaxf(mt1, __shfl_xor_sync(0xffffffffu, mt1, off));
                }
                const float mn0 = fmaxf(m[mi][0], mt0);
                const float mn1 = fmaxf(m[mi][1], mt1);
                const float al0 = exp2f(m[mi][0] - mn0);
                const float al1 = exp2f(m[mi][1] - mn1);
                m[mi][0] = mn0; m[mi][1] = mn1;
                float rs0 = 0.0f, rs1 = 0.0f;
#pragma unroll
                for (int j = 0; j < 8; j++) {
                    sreg[mi][j][0] = exp2f(sreg[mi][j][0] - mn0);
                    sreg[mi][j][1] = exp2f(sreg[mi][j][1] - mn0);
                    sreg[mi][j][2] = exp2f(sreg[mi][j][2] - mn1);
                    sreg[mi][j][3] = exp2f(sreg[mi][j][3] - mn1);
                    rs0 += sreg[mi][j][0] + sreg[mi][j][1];
                    rs1 += sreg[mi][j][2] + sreg[mi][j][3];
                }
#pragma unroll
                for (int off = 1; off <= 2; off <<= 1) {
                    rs0 += __shfl_xor_sync(0xffffffffu, rs0, off);
                    rs1 += __shfl_xor_sync(0xffffffffu, rs1, off);
                }
                l[mi][0] = l[mi][0] * al0 + rs0;
                l[mi][1] = l[mi][1] * al1 + rs1;
#pragma unroll
                for (int j = 0; j < 8; j++) {
                    o[mi][j][0] *= al0; o[mi][j][1] *= al0;
                    o[mi][j][2] *= al1; o[mi][j][3] *= al1;
                }
            }

            // O += P @ V — P straight from registers.
            // A-fragment slot qc holds P col (2qc), slot qc+4 holds col (2qc+1);
            // V smem rows were permuted to match (row qc = seq 2qc, row qc+4 = seq 2qc+1).
#pragma unroll
            for (int ks = 0; ks < 8; ks++) {
                uint32_t pa0[4], pa1[4];
                pa0[0] = f2tf32(sreg[0][ks][0]); pa0[1] = f2tf32(sreg[0][ks][2]);
                pa0[2] = f2tf32(sreg[0][ks][1]); pa0[3] = f2tf32(sreg[0][ks][3]);
                pa1[0] = f2tf32(sreg[1][ks][0]); pa1[1] = f2tf32(sreg[1][ks][2]);
                pa1[2] = f2tf32(sreg[1][ks][1]); pa1[3] = f2tf32(sreg[1][ks][3]);
#pragma unroll
                for (int j = 0; j < 8; j++) {
                    const uint32_t b0 = Vs[(ks * 8 + qc) * VST + j * 8 + qr];
                    const uint32_t b1 = Vs[(ks * 8 + 4 + qc) * VST + j * 8 + qr];
                    mma_tf32(o[0][j], pa0, b0, b1);
                    mma_tf32(o[1][j], pa1, b0, b1);
                }
            }
        }
    }

    // epilogue: V cols were hd-permuted, so face-position writes give the
    // K-permuted layout the out-proj GEMM expects.
    float* ob = out + ((size_t)(b * LL + qt * 128 + w * 32)) * DD + h * HD;
#pragma unroll
    for (int mi = 0; mi < 2; mi++) {
        const float inv0 = 1.0f / l[mi][0];
        const float inv1 = 1.0f / l[mi][1];
        const size_t r0 = (size_t)(mi * 16 + qr) * DD;
#pragma unroll
        for (int j = 0; j < 8; j++) {
            const int col = j * 8 + qc * 2;
            uint2 v0 = make_uint2(f2tf32(o[mi][j][0] * inv0), f2tf32(o[mi][j][1] * inv0));
            uint2 v1 = make_uint2(f2tf32(o[mi][j][2] * inv1), f2tf32(o[mi][j][3] * inv1));
            *(uint2*)(ob + r0 + col)          = v0;
            *(uint2*)(ob + r0 + 8 * DD + col) = v1;
        }
    }
}

// ---------------------------------------------------------------------------
extern "C" void kernel_launch(void* const* d_in, const int* in_sizes, int n_in,
                              void* d_out, int out_size)
{
    const float* x    = (const float*)d_in[0];
    const float* Wqkv = (const float*)d_in[1];
    const float* bqkv = (const float*)d_in[2];
    const float* Wout = (const float*)d_in[3];
    const float* bout = (const float*)d_in[4];
    float* outp = (float*)d_out;

    float *qkv = nullptr, *att = nullptr, *bq = nullptr;
    uint32_t *xt = nullptr, *wq = nullptr, *wo = nullptr;
    cudaGetSymbolAddress((void**)&qkv, g_qkv);
    cudaGetSymbolAddress((void**)&att, g_att);
    cudaGetSymbolAddress((void**)&xt, g_xt);
    cudaGetSymbolAddress((void**)&wq, g_wq);
    cudaGetSymbolAddress((void**)&wo, g_wo);
    cudaGetSymbolAddress((void**)&bq, g_bq);

    static bool attr_set = false;
    if (!attr_set) {
        cudaFuncSetAttribute(attn_tf32_kernel,
                             cudaFuncAttributeMaxDynamicSharedMemorySize, SMEM_ATTN);
        cudaFuncSetAttribute(gemm_tf32<0>,
                             cudaFuncAttributeMaxDynamicSharedMemorySize, SMEM_GEMM);
        cudaFuncSetAttribute(gemm_tf32<1>,
                             cudaFuncAttributeMaxDynamicSharedMemorySize, SMEM_GEMM);
        attr_set = true;
    }

    const int M = BB * LL;  // 8192

    // prepass: tf32 + K-permutation (+ row perm for Wqkv), bias perm
    {
        int ng = (M * DD) / 8;
        perm_tf32_kernel<0><<<(ng + 255) / 256, 256>>>(x, xt, M, DD);
        ng = (3 * DD * DD) / 8;
        perm_tf32_kernel<1><<<(ng + 255) / 256, 256>>>(Wqkv, wq, 3 * DD, DD);
        ng = (DD * DD) / 8;
        perm_tf32_kernel<0><<<(ng + 255) / 256, 256>>>(Wout, wo, DD, DD);
        perm_bias_kernel<<<12, 256>>>(bqkv, bq, 3 * DD);
    }

    // 1) QKV projection (tf32 bits out, Q pre-scaled by QSCALE, hd-permuted)
    {
        dim3 grid((3 * DD) / 128, M / 128);
        gemm_tf32<1><<<grid, 128, SMEM_GEMM>>>(xt, wq, bq, qkv, M, 3 * DD, DD);
    }

    // 2) causal attention
    {
        dim3 grid(LL / 128, HH, BB);
        attn_tf32_kernel<<<grid, 128, SMEM_ATTN>>>(qkv, att);
    }

    // 3) output projection (fp32 out)
    {
        dim3 grid(DD / 128, M / 128);
        gemm_tf32<0><<<grid, 128, SMEM_GEMM>>>((const uint32_t*)att, wo, bout, outp, M, DD, DD);
    }
}